// round 6
// baseline (speedup 1.0000x reference)
#include <cuda_runtime.h>
#include <cuda_bf16.h>
#include <cstdint>

// Correlation cost volume via warp-specialized bf16 tensor MMA (3-way split).
//   out[b,i,h,x] = (1/128) * sum_c L[b,c,h,x] * R[b,c,h,x-i],  x>=i, else 0
// b=8, c=128, h=96, w=320, D=48.
//
// Per (b,h), 128-wide x tile: D[m,n] = sum_k A[m,k]B[n,k],
// A[m,k]=L[k, X+m], B[n,k]=R[k, X-48+n]; out(i, X+m) = D[m, m+48-i]/128.
// fp32 = hi(bf16)+lo(bf16); D += Ah*Bh + Ah*Bl + Al*Bh.
// Warps 4-7 stage 32-channel chunks (double buffered); warps 0-3 each own a
// m32 row-group with an 80-row shared B window (cuts smem re-read ~30%).

namespace {
constexpr int kB = 8, kC = 128, kH = 96, kW = 320, kD = 48;
constexpr int CHW = kH * kW;            // 30720
constexpr int TM = 128;                 // x per CTA tile
constexpr int TN = 176;                 // x' rows staged
constexpr int NT = 256;                 // 4 consumer + 4 producer warps

// chunk = 32 channels; row = 64B (32 bf16) per half buffer
constexpr int OFF_AH = 0;               // 128*64
constexpr int OFF_AL = 8192;
constexpr int OFF_BH = 16384;           // 176*64
constexpr int OFF_BL = 27648;
constexpr int BUFB   = 38912;           // one chunk buffer
constexpr int SMEM_TOTAL = 2 * BUFB;    // 77824 (bounce overlays later)
constexpr int BNC_PITCH = 81;           // floats per bounce row

// named barriers (0 = __syncthreads)
constexpr int BAR_FULL0 = 1, BAR_FULL1 = 2, BAR_EMPTY0 = 3, BAR_EMPTY1 = 4;
constexpr int BAR_CONS = 5;
}

__device__ __forceinline__ uint32_t smem_u32(const void* p) {
    uint32_t a;
    asm("{ .reg .u64 t; cvta.to.shared.u64 t, %1; cvt.u32.u64 %0, t; }" : "=r"(a) : "l"(p));
    return a;
}
__device__ __forceinline__ void bar_sync(int id, int cnt) {
    asm volatile("bar.sync %0, %1;" :: "r"(id), "r"(cnt) : "memory");
}
__device__ __forceinline__ void bar_arrive(int id, int cnt) {
    asm volatile("bar.arrive %0, %1;" :: "r"(id), "r"(cnt) : "memory");
}
__device__ __forceinline__ void ldsm_x4(uint32_t* r, uint32_t addr) {
    asm volatile("ldmatrix.sync.aligned.m8n8.x4.shared.b16 {%0,%1,%2,%3}, [%4];"
                 : "=r"(r[0]), "=r"(r[1]), "=r"(r[2]), "=r"(r[3]) : "r"(addr));
}
__device__ __forceinline__ void mma_bf16(float* d, const uint32_t* a, const uint32_t* b) {
    asm volatile(
        "mma.sync.aligned.m16n8k16.row.col.f32.bf16.bf16.f32 "
        "{%0,%1,%2,%3}, {%4,%5,%6,%7}, {%8,%9}, {%0,%1,%2,%3};"
        : "+f"(d[0]), "+f"(d[1]), "+f"(d[2]), "+f"(d[3])
        : "r"(a[0]), "r"(a[1]), "r"(a[2]), "r"(a[3]), "r"(b[0]), "r"(b[1]));
}
// acc += Ah*Bh + Ah*Bl + Al*Bh
__device__ __forceinline__ void mma3(float* d, const uint32_t* ah, const uint32_t* al,
                                     const uint32_t* bh, const uint32_t* bl) {
    mma_bf16(d, ah, bh);
    mma_bf16(d, ah, bl);
    mma_bf16(d, al, bh);
}

// fp32x4 -> hi bf16x4 packed + residuals
__device__ __forceinline__ uint2 split_hi(float f0, float f1, float f2, float f3,
                                          float& r0, float& r1, float& r2, float& r3) {
    __nv_bfloat162 a = __floats2bfloat162_rn(f0, f1);
    __nv_bfloat162 b = __floats2bfloat162_rn(f2, f3);
    r0 = f0 - __bfloat162float(a.x);
    r1 = f1 - __bfloat162float(a.y);
    r2 = f2 - __bfloat162float(b.x);
    r3 = f3 - __bfloat162float(b.y);
    uint2 v;
    v.x = *reinterpret_cast<uint32_t*>(&a);
    v.y = *reinterpret_cast<uint32_t*>(&b);
    return v;
}
__device__ __forceinline__ uint2 pack_lo(float r0, float r1, float r2, float r3) {
    __nv_bfloat162 a = __floats2bfloat162_rn(r0, r1);
    __nv_bfloat162 b = __floats2bfloat162_rn(r2, r3);
    uint2 v;
    v.x = *reinterpret_cast<uint32_t*>(&a);
    v.y = *reinterpret_cast<uint32_t*>(&b);
    return v;
}

// pitch-64 swizzle: 16B line index ^= (row>>1)&3 -> any 8 consecutive rows hit
// 8 distinct 16B slots per 128B (CF for STS.128 and ldmatrix phases)
__device__ __forceinline__ uint32_t swoff(uint32_t row, uint32_t line) {
    return row * 64u + ((line ^ ((row >> 1) & 3u)) << 4);
}

extern __shared__ char smem[];

__global__ __launch_bounds__(NT, 2)
void costvol_ws(const float* __restrict__ L, const float* __restrict__ R,
                float* __restrict__ out) {
    const uint32_t sb = smem_u32(smem);
    const int tid = threadIdx.x;
    const int wid = tid >> 5;
    const int lid = tid & 31;

    const int tile = blockIdx.x;            // 0..2
    const int bh   = blockIdx.y;            // 0..767
    const int b = bh / kH;
    const int h = bh - b * kH;
    const int X = tile * TM;

    if (wid >= 4) {
        // ================= PRODUCER (warps 4-7) =================
        const int ptid = tid - 128;
#pragma unroll 1
        for (int k = 0; k < 4; k++) {
            const int buf = k & 1;
            if (k >= 2) bar_sync(BAR_EMPTY0 + buf, NT);
            const uint32_t base = sb + buf * BUFB;
            const int c0 = 32 * k;
            // A: 128 rows x 4 groups (8 ch each) = 512 slots
#pragma unroll
            for (int s = ptid; s < 512; s += 128) {
                const int row = s & 127;
                const int g8  = s >> 7;
                const bool ok = (X + row) < kW;
                const float* p = L + ((long)(b * kC + c0 + 8 * g8) * kH + h) * kW + X + row;
                float f[8];
#pragma unroll
                for (int j = 0; j < 8; j++) f[j] = ok ? p[j * CHW] : 0.f;
                float r[8];
                const uint2 h0 = split_hi(f[0], f[1], f[2], f[3], r[0], r[1], r[2], r[3]);
                const uint2 h1 = split_hi(f[4], f[5], f[6], f[7], r[4], r[5], r[6], r[7]);
                const uint2 l0 = pack_lo(r[0], r[1], r[2], r[3]);
                const uint2 l1 = pack_lo(r[4], r[5], r[6], r[7]);
                const uint32_t off = swoff((uint32_t)row, (uint32_t)g8);
                uint4 hv; hv.x = h0.x; hv.y = h0.y; hv.z = h1.x; hv.w = h1.y;
                uint4 lv; lv.x = l0.x; lv.y = l0.y; lv.z = l1.x; lv.w = l1.y;
                *reinterpret_cast<uint4*>(smem + buf * BUFB + OFF_AH + off) = hv;
                *reinterpret_cast<uint4*>(smem + buf * BUFB + OFF_AL + off) = lv;
            }
            // B: 176 rows x 4 groups = 704 slots
#pragma unroll 1
            for (int s = ptid; s < 704; s += 128) {
                const int g8  = s / 176;
                const int row = s - g8 * 176;
                const int xp  = X - kD + row;
                const bool ok = (xp >= 0) && (xp < kW);
                const float* p = R + ((long)(b * kC + c0 + 8 * g8) * kH + h) * kW
                               + (ok ? xp : 0);
                float f[8];
#pragma unroll
                for (int j = 0; j < 8; j++) f[j] = ok ? p[j * CHW] : 0.f;
                float r[8];
                const uint2 h0 = split_hi(f[0], f[1], f[2], f[3], r[0], r[1], r[2], r[3]);
                const uint2 h1 = split_hi(f[4], f[5], f[6], f[7], r[4], r[5], r[6], r[7]);
                const uint2 l0 = pack_lo(r[0], r[1], r[2], r[3]);
                const uint2 l1 = pack_lo(r[4], r[5], r[6], r[7]);
                const uint32_t off = swoff((uint32_t)row, (uint32_t)g8);
                uint4 hv; hv.x = h0.x; hv.y = h0.y; hv.z = h1.x; hv.w = h1.y;
                uint4 lv; lv.x = l0.x; lv.y = l0.y; lv.z = l1.x; lv.w = l1.y;
                *reinterpret_cast<uint4*>(smem + buf * BUFB + OFF_BH + off) = hv;
                *reinterpret_cast<uint4*>(smem + buf * BUFB + OFF_BL + off) = lv;
            }
            bar_arrive(BAR_FULL0 + buf, NT);
        }
    } else {
        // ================= CONSUMER (warps 0-3) =================
        const int g = wid;                   // m rows [32g, 32g+32)
        float acc0[8][4], acc1[8][4];
#pragma unroll
        for (int j = 0; j < 8; j++)
#pragma unroll
            for (int q = 0; q < 4; q++) { acc0[j][q] = 0.f; acc1[j][q] = 0.f; }

        // A lane rows (two m16 tiles), B lane rows within each 16-row group
        const uint32_t rowA0 = 32u * g + (lid & 15);
        const uint32_t rowA1 = rowA0 + 16u;
        const uint32_t aHalf = (uint32_t)(lid >> 4);
        const uint32_t bRow  = 8u * (uint32_t)(lid >> 4) + (lid & 7);
        const uint32_t bHalf = (uint32_t)((lid >> 3) & 1);

#pragma unroll 1
        for (int k = 0; k < 4; k++) {
            const int buf = k & 1;
            bar_sync(BAR_FULL0 + buf, NT);
            const uint32_t base = sb + buf * BUFB;
#pragma unroll
            for (int ks = 0; ks < 2; ks++) {
                uint32_t ah0[4], al0[4], ah1[4], al1[4];
                const uint32_t aoff0 = swoff(rowA0, 2u * ks + aHalf);
                const uint32_t aoff1 = swoff(rowA1, 2u * ks + aHalf);
                ldsm_x4(ah0, base + OFF_AH + aoff0);
                ldsm_x4(al0, base + OFF_AL + aoff0);
                ldsm_x4(ah1, base + OFF_AH + aoff1);
                ldsm_x4(al1, base + OFF_AL + aoff1);
#pragma unroll
                for (int jp = 0; jp < 5; jp++) {
                    uint32_t bh4[4], bl4[4];
                    const uint32_t rB = 32u * g + 16u * jp + bRow;
                    const uint32_t boff = swoff(rB, 2u * ks + bHalf);
                    ldsm_x4(bh4, base + OFF_BH + boff);
                    ldsm_x4(bl4, base + OFF_BL + boff);
                    const int f0 = 2 * jp, f1 = 2 * jp + 1;
                    if (f0 < 8) mma3(acc0[f0], ah0, al0, bh4,     bl4);
                    if (f1 < 8) mma3(acc0[f1], ah0, al0, bh4 + 2, bl4 + 2);
                    if (f0 >= 2) mma3(acc1[f0 - 2], ah1, al1, bh4,     bl4);
                    if (f1 >= 2) mma3(acc1[f1 - 2], ah1, al1, bh4 + 2, bl4 + 2);
                }
            }
            if (k < 2) bar_arrive(BAR_EMPTY0 + buf, NT);
        }

        // all consumers done with buffers before bounce overlays smem
        bar_sync(BAR_CONS, 128);

        // acc -> bounce (scaled); warp g rows [32g,32g+32), cols n-32g in [0,80)
        float* bnc = reinterpret_cast<float*>(smem);
        const float sc = 1.0f / (float)kC;
        const int q = lid >> 2;
        const int e = lid & 3;
#pragma unroll
        for (int t = 0; t < 2; t++) {
#pragma unroll
            for (int j = 0; j < 8; j++) {
                const float* a4 = (t == 0) ? acc0[j] : acc1[j];
                const int col = 8 * (j + 2 * t) + 2 * e;
                const int m0 = 32 * g + 16 * t + q;
                bnc[m0 * BNC_PITCH + col]           = a4[0] * sc;
                bnc[m0 * BNC_PITCH + col + 1]       = a4[1] * sc;
                bnc[(m0 + 8) * BNC_PITCH + col]     = a4[2] * sc;
                bnc[(m0 + 8) * BNC_PITCH + col + 1] = a4[3] * sc;
            }
        }
    }

    __syncthreads();

    // out[b,i,h,X+xl] = bounce[xl][(xl&31) + 48 - i], coalesced in x
    const int xl = tid & 127;
    if (X + xl < kW) {
        const float* bnr = reinterpret_cast<const float*>(smem)
                         + xl * BNC_PITCH + (xl & 31) + 48;
        float* ob = out + (long)(b * kD) * CHW + h * kW + X + xl;
#pragma unroll
        for (int it = 0; it < 24; it++) {
            const int i = 2 * it + (tid >> 7);
            ob[(long)i * CHW] = bnr[-i];
        }
    }
}

extern "C" void kernel_launch(void* const* d_in, const int* in_sizes, int n_in,
                              void* d_out, int out_size) {
    const float* L = (const float*)d_in[0];
    const float* R = (const float*)d_in[1];
    float* out = (float*)d_out;

    cudaFuncSetAttribute(costvol_ws,
                         cudaFuncAttributeMaxDynamicSharedMemorySize, SMEM_TOTAL);

    dim3 grid((kW + TM - 1) / TM, kB * kH);   // (3, 768) = 2304 CTAs
    costvol_ws<<<grid, NT, SMEM_TOTAL>>>(L, R, out);
}

// round 7
// speedup vs baseline: 1.7181x; 1.7181x over previous
#include <cuda_runtime.h>
#include <cuda_bf16.h>
#include <cstdint>

// Correlation cost volume via bf16 tensor MMA (3-way bf16 split of fp32).
//   out[b,i,h,x] = (1/128) * sum_c L[b,c,h,x] * R[b,c,h,x-i],  x>=i, else 0
// b=8, c=128, h=96, w=320, D=48.
//
// Per (b,h), 128-wide x tile: D[m,n] = sum_k A[m,k]B[n,k],
// A[m,k]=L[k, X+m], B[n,k]=R[k, X-48+n]; out(i, X+m) = D[m, m+48-i]/128.
// fp32 = hi(bf16)+lo(bf16); D += Ah*Bh + Ah*Bl + Al*Bh.
//
// R7: homogeneous warps (R5 scheme — every warp stages AND computes), K in
// 4 chunks of 32 channels, double-buffered smem, LDGs for chunk k+1 issued
// before MMAs on chunk k (register prefetch) to hide DRAM latency.

namespace {
constexpr int kB = 8, kC = 128, kH = 96, kW = 320, kD = 48;
constexpr int CHW = kH * kW;            // 30720
constexpr int TM = 128;                 // x per CTA tile
constexpr int TN = 176;                 // x' rows staged
constexpr int NT = 256;                 // 8 warps; warp wid owns m16 tile

// chunk = 32 channels; row = 64 B (32 bf16) per hi/lo half
constexpr int OFF_AH = 0;               // 128*64 = 8192
constexpr int OFF_AL = 8192;
constexpr int OFF_BH = 16384;           // 176*64 = 11264
constexpr int OFF_BL = 27648;
constexpr int BUFB   = 38912;
constexpr int SMEM_TOTAL = 2 * BUFB;    // 77824; bounce overlays at the end
constexpr int BNC_PITCH = 81;           // floats per bounce row (CF diagonals)
constexpr int NCHUNK = 4;
}

__device__ __forceinline__ uint32_t smem_u32(const void* p) {
    uint32_t a;
    asm("{ .reg .u64 t; cvta.to.shared.u64 t, %1; cvt.u32.u64 %0, t; }" : "=r"(a) : "l"(p));
    return a;
}
__device__ __forceinline__ void ldsm_x4(uint32_t* r, uint32_t addr) {
    asm volatile("ldmatrix.sync.aligned.m8n8.x4.shared.b16 {%0,%1,%2,%3}, [%4];"
                 : "=r"(r[0]), "=r"(r[1]), "=r"(r[2]), "=r"(r[3]) : "r"(addr));
}
__device__ __forceinline__ void mma_bf16(float* d, const uint32_t* a, const uint32_t* b) {
    asm volatile(
        "mma.sync.aligned.m16n8k16.row.col.f32.bf16.bf16.f32 "
        "{%0,%1,%2,%3}, {%4,%5,%6,%7}, {%8,%9}, {%0,%1,%2,%3};"
        : "+f"(d[0]), "+f"(d[1]), "+f"(d[2]), "+f"(d[3])
        : "r"(a[0]), "r"(a[1]), "r"(a[2]), "r"(a[3]), "r"(b[0]), "r"(b[1]));
}
__device__ __forceinline__ void mma3(float* d, const uint32_t* ah, const uint32_t* al,
                                     const uint32_t* bh, const uint32_t* bl) {
    mma_bf16(d, ah, bh);
    mma_bf16(d, ah, bl);
    mma_bf16(d, al, bh);
}

// fp32x4 -> hi bf16x4 packed + residuals
__device__ __forceinline__ uint2 split_hi(float f0, float f1, float f2, float f3,
                                          float& r0, float& r1, float& r2, float& r3) {
    __nv_bfloat162 a = __floats2bfloat162_rn(f0, f1);
    __nv_bfloat162 b = __floats2bfloat162_rn(f2, f3);
    r0 = f0 - __bfloat162float(a.x);
    r1 = f1 - __bfloat162float(a.y);
    r2 = f2 - __bfloat162float(b.x);
    r3 = f3 - __bfloat162float(b.y);
    uint2 v;
    v.x = *reinterpret_cast<uint32_t*>(&a);
    v.y = *reinterpret_cast<uint32_t*>(&b);
    return v;
}
__device__ __forceinline__ uint2 pack_lo(float r0, float r1, float r2, float r3) {
    __nv_bfloat162 a = __floats2bfloat162_rn(r0, r1);
    __nv_bfloat162 b = __floats2bfloat162_rn(r2, r3);
    uint2 v;
    v.x = *reinterpret_cast<uint32_t*>(&a);
    v.y = *reinterpret_cast<uint32_t*>(&b);
    return v;
}

// pitch-64 swizzle: 16B line ^= (row>>1)&3 -> any 8 consecutive rows hit 8
// distinct 16B slots per 128B (CF for STS.128 and all ldmatrix phases).
__device__ __forceinline__ uint32_t swoff(uint32_t row, uint32_t line) {
    return row * 64u + ((line ^ ((row >> 1) & 3u)) << 4);
}

extern __shared__ char smem[];

__global__ __launch_bounds__(NT, 2)
void costvol_pipe(const float* __restrict__ L, const float* __restrict__ R,
                  float* __restrict__ out) {
    const uint32_t sb = smem_u32(smem);
    const int tid = threadIdx.x;
    const int wid = tid >> 5;
    const int lid = tid & 31;

    const int tile = blockIdx.x;            // 0..2
    const int bh   = blockIdx.y;            // 0..767
    const int b = bh / kH;
    const int h = bh - b * kH;
    const int X = tile * TM;

    // ---- staging slot geometry (per thread): A 2 slots, B 3 slots (last partial)
    // A slot s in [0,512): row = s&127, g8 = s>>7.  B slot s in [0,704).
    const int sA0 = tid,       sA1 = tid + 256;
    const int sB0 = tid,       sB1 = tid + 256,  sB2 = tid + 512;   // sB2 valid if tid<192

    const int rowA0s = sA0 & 127, g8A0 = sA0 >> 7;
    const int rowA1s = sA1 & 127, g8A1 = sA1 >> 7;
    const int g8B0 = sB0 / TN, rowB0 = sB0 - g8B0 * TN;
    const int g8B1 = sB1 / TN, rowB1 = sB1 - g8B1 * TN;
    const int g8B2 = sB2 / TN, rowB2 = sB2 - g8B2 * TN;
    const bool vB2 = (sB2 < 704);

    const bool okA0 = (X + rowA0s) < kW;
    const bool okA1 = (X + rowA1s) < kW;
    const int xpB0 = X - kD + rowB0;  const bool okB0 = (xpB0 >= 0) && (xpB0 < kW);
    const int xpB1 = X - kD + rowB1;  const bool okB1 = (xpB1 >= 0) && (xpB1 < kW);
    const int xpB2 = X - kD + rowB2;  const bool okB2 = vB2 && (xpB2 >= 0) && (xpB2 < kW);

    const float* Lb = L + ((long)(b * kC) * kH + h) * kW;   // + c*CHW + x
    const float* Rb = R + ((long)(b * kC) * kH + h) * kW;

    float fA0[8], fA1[8], fB0[8], fB1[8], fB2[8];

    auto loads = [&](int k) {
        const int c0 = 32 * k;
        const float* pA0 = Lb + (long)(c0 + 8 * g8A0) * CHW + X + rowA0s;
        const float* pA1 = Lb + (long)(c0 + 8 * g8A1) * CHW + X + rowA1s;
        const float* pB0 = Rb + (long)(c0 + 8 * g8B0) * CHW + (okB0 ? xpB0 : 0);
        const float* pB1 = Rb + (long)(c0 + 8 * g8B1) * CHW + (okB1 ? xpB1 : 0);
        const float* pB2 = Rb + (long)(c0 + 8 * (vB2 ? g8B2 : 0)) * CHW + (okB2 ? xpB2 : 0);
#pragma unroll
        for (int j = 0; j < 8; j++) {
            fA0[j] = okA0 ? pA0[j * CHW] : 0.f;
            fA1[j] = okA1 ? pA1[j * CHW] : 0.f;
            fB0[j] = okB0 ? pB0[j * CHW] : 0.f;
            fB1[j] = okB1 ? pB1[j * CHW] : 0.f;
            fB2[j] = okB2 ? pB2[j * CHW] : 0.f;
        }
    };

    auto cvt_store = [&](const float* f, int base_off, int row, int g8) {
        float r[8];
        const uint2 h0 = split_hi(f[0], f[1], f[2], f[3], r[0], r[1], r[2], r[3]);
        const uint2 h1 = split_hi(f[4], f[5], f[6], f[7], r[4], r[5], r[6], r[7]);
        const uint2 l0 = pack_lo(r[0], r[1], r[2], r[3]);
        const uint2 l1 = pack_lo(r[4], r[5], r[6], r[7]);
        const uint32_t off = swoff((uint32_t)row, (uint32_t)g8);
        uint4 hv; hv.x = h0.x; hv.y = h0.y; hv.z = h1.x; hv.w = h1.y;
        uint4 lv; lv.x = l0.x; lv.y = l0.y; lv.z = l1.x; lv.w = l1.y;
        *reinterpret_cast<uint4*>(smem + base_off + off)        = hv;   // hi
        *reinterpret_cast<uint4*>(smem + base_off + 8192 + ((base_off & 16384) ? 3072 : 0) + off) = lv; // lo
    };

    auto stage = [&](int buf) {
        const int bo = buf * BUFB;
        cvt_store(fA0, bo + OFF_AH, rowA0s, g8A0);
        cvt_store(fA1, bo + OFF_AH, rowA1s, g8A1);
        cvt_store(fB0, bo + OFF_BH, rowB0, g8B0);
        cvt_store(fB1, bo + OFF_BH, rowB1, g8B1);
        if (vB2) cvt_store(fB2, bo + OFF_BH, rowB2, g8B2);
    };

    // ---- consumer: warp wid owns m rows [16wid,16wid+16), B window 64 rows
    float acc[8][4];
#pragma unroll
    for (int j = 0; j < 8; j++)
#pragma unroll
        for (int q = 0; q < 4; q++) acc[j][q] = 0.f;

    const uint32_t rowA = 16u * wid + (lid & 15);
    const uint32_t aHalf = (uint32_t)(lid >> 4);
    const uint32_t bRow  = 8u * (uint32_t)(lid >> 4) + (lid & 7);
    const uint32_t bHalf = (uint32_t)((lid >> 3) & 1);

    auto domma = [&](int buf) {
        const uint32_t base = sb + buf * BUFB;
#pragma unroll
        for (int ks = 0; ks < 2; ks++) {
            uint32_t ah[4], al[4];
            const uint32_t aoff = swoff(rowA, 2u * ks + aHalf);
            ldsm_x4(ah, base + OFF_AH + aoff);
            ldsm_x4(al, base + OFF_AL + aoff);
#pragma unroll
            for (int jp = 0; jp < 4; jp++) {
                uint32_t bh4[4], bl4[4];
                const uint32_t rB = 16u * wid + 16u * jp + bRow;
                const uint32_t boff = swoff(rB, 2u * ks + bHalf);
                ldsm_x4(bh4, base + OFF_BH + boff);
                ldsm_x4(bl4, base + OFF_BL + boff);
                mma3(acc[2 * jp],     ah, al, bh4,     bl4);
                mma3(acc[2 * jp + 1], ah, al, bh4 + 2, bl4 + 2);
            }
        }
    };

    // ---- pipeline: prefetch LDG(k+1) before mma(k), convert after ----
    loads(0);
    stage(0);
    __syncthreads();
#pragma unroll
    for (int k = 0; k < NCHUNK; k++) {
        if (k + 1 < NCHUNK) loads(k + 1);      // LDGs in flight during MMA
        domma(k & 1);
        if (k + 1 < NCHUNK) stage((k + 1) & 1);
        __syncthreads();
    }

    // ---- acc -> bounce (scaled): warp wid rows [16wid,16wid+16), 64 cols ----
    {
        float* bnc = reinterpret_cast<float*>(smem);
        const float sc = 1.0f / (float)kC;
        const int q = lid >> 2;
        const int e = lid & 3;
        const int m0 = 16 * wid + q;
#pragma unroll
        for (int j = 0; j < 8; j++) {
            const int col = 8 * j + 2 * e;
            bnc[m0 * BNC_PITCH + col]           = acc[j][0] * sc;
            bnc[m0 * BNC_PITCH + col + 1]       = acc[j][1] * sc;
            bnc[(m0 + 8) * BNC_PITCH + col]     = acc[j][2] * sc;
            bnc[(m0 + 8) * BNC_PITCH + col + 1] = acc[j][3] * sc;
        }
    }
    __syncthreads();

    // ---- out[b,i,h,X+xl] = bounce[xl][(xl&15) + 48 - i], coalesced in x ----
    const int xl = tid & 127;
    if (X + xl < kW) {
        const float* bnr = reinterpret_cast<const float*>(smem)
                         + xl * BNC_PITCH + (xl & 15) + 48;
        float* ob = out + (long)(b * kD) * CHW + h * kW + X + xl;
#pragma unroll
        for (int it = 0; it < 24; it++) {
            const int i = 2 * it + (tid >> 7);
            ob[(long)i * CHW] = bnr[-i];
        }
    }
}

extern "C" void kernel_launch(void* const* d_in, const int* in_sizes, int n_in,
                              void* d_out, int out_size) {
    const float* L = (const float*)d_in[0];
    const float* R = (const float*)d_in[1];
    float* out = (float*)d_out;

    cudaFuncSetAttribute(costvol_pipe,
                         cudaFuncAttributeMaxDynamicSharedMemorySize, SMEM_TOTAL);

    dim3 grid((kW + TM - 1) / TM, kB * kH);   // (3, 768) = 2304 CTAs
    costvol_pipe<<<grid, NT, SMEM_TOTAL>>>(L, R, out);
}